// round 13
// baseline (speedup 1.0000x reference)
#include <cuda_runtime.h>
#include <cuda_bf16.h>
#include <cstdint>
#include <math.h>

#define NB 4
#define NHW 4096
#define NC 256
#define NTOK (NB*NHW)   // 16384

// ================= scratch =================
__device__ __nv_bfloat16 g_attnh[NTOK*NC];
__device__ __nv_bfloat16 g_qh[NTOK*NC];
__device__ __nv_bfloat16 g_kh[NTOK*NC];
__device__ __nv_bfloat16 g_vh[NTOK*NC];
__device__ __nv_bfloat16 g_wh[4*NC*NC];   // bf16 wq|wk|wv|wp
__device__ float g_part[512];

// ================= helpers =================
__device__ __forceinline__ uint32_t smem_to_u32(const void* p) {
    uint32_t a;
    asm("{ .reg .u64 t; cvta.to.shared.u64 t, %1; cvt.u32.u64 %0, t; }" : "=r"(a) : "l"(p));
    return a;
}
#define CP_ASYNC16(saddr, gptr) \
    asm volatile("cp.async.cg.shared.global [%0], [%1], 16;" :: "r"(saddr), "l"(gptr))
#define CP_COMMIT()  asm volatile("cp.async.commit_group;" ::: "memory")
#define CP_WAIT0()   asm volatile("cp.async.wait_group 0;" ::: "memory")
#define CP_WAIT1()   asm volatile("cp.async.wait_group 1;" ::: "memory")

__device__ __forceinline__ void ldsm_x4(uint32_t* r, uint32_t addr) {
    asm volatile("ldmatrix.sync.aligned.m8n8.x4.shared.b16 {%0,%1,%2,%3}, [%4];"
        : "=r"(r[0]), "=r"(r[1]), "=r"(r[2]), "=r"(r[3]) : "r"(addr));
}
__device__ __forceinline__ void ldsm_x4_t(uint32_t* r, uint32_t addr) {
    asm volatile("ldmatrix.sync.aligned.m8n8.x4.trans.shared.b16 {%0,%1,%2,%3}, [%4];"
        : "=r"(r[0]), "=r"(r[1]), "=r"(r[2]), "=r"(r[3]) : "r"(addr));
}
__device__ __forceinline__ void mma16816(float* d, const uint32_t* a, uint32_t b0, uint32_t b1) {
    asm volatile("mma.sync.aligned.m16n8k16.row.col.f32.bf16.bf16.f32 "
        "{%0,%1,%2,%3}, {%4,%5,%6,%7}, {%8,%9}, {%0,%1,%2,%3};"
        : "+f"(d[0]), "+f"(d[1]), "+f"(d[2]), "+f"(d[3])
        : "r"(a[0]), "r"(a[1]), "r"(a[2]), "r"(a[3]), "r"(b0), "r"(b1));
}
__device__ __forceinline__ float ex2f(float x) {
    float y;
    asm("ex2.approx.ftz.f32 %0, %1;" : "=f"(y) : "f"(x));
    return y;
}

// ================= Stage 1: GN partial sums (blocks 0-255) + weight convert (blocks 256-511) =================
__global__ __launch_bounds__(256) void gn_stats_convw(const float* __restrict__ x,
                                                      const float* __restrict__ w0,
                                                      const float* __restrict__ w1,
                                                      const float* __restrict__ w2,
                                                      const float* __restrict__ w3) {
    int blk = blockIdx.x;
    int t = threadIdx.x;
    if (blk >= 256) {
        int i = (blk - 256) * 256 + t;
        int which = i >> 14, off = i & 16383;
        const float* src = which == 0 ? w0 : which == 1 ? w1 : which == 2 ? w2 : w3;
        float4 v = ((const float4*)src)[off];
        uint32_t p0, p1;
        asm("cvt.rn.satfinite.bf16x2.f32 %0, %1, %2;" : "=r"(p0) : "f"(v.y), "f"(v.x));
        asm("cvt.rn.satfinite.bf16x2.f32 %0, %1, %2;" : "=r"(p1) : "f"(v.w), "f"(v.z));
        *(uint2*)(g_wh + (size_t)which * 65536 + off * 4) = make_uint2(p0, p1);
        return;
    }
    int bg = blk >> 3, seg = blk & 7;
    int b = bg >> 3, g = bg & 7;
    const float* xb = x + (size_t)b * NHW * NC + (size_t)(seg * 512) * NC + g * 32;
    float s = 0.f, ss = 0.f;
    for (int idx = t; idx < 4096; idx += 256) {
        int p = idx >> 3, cq = idx & 7;
        float4 v = *(const float4*)(xb + (size_t)p * NC + 4 * cq);
        s  += v.x + v.y + v.z + v.w;
        ss += v.x*v.x + v.y*v.y + v.z*v.z + v.w*v.w;
    }
    __shared__ float rs[256], rq[256];
    rs[t] = s; rq[t] = ss;
    __syncthreads();
    for (int st = 128; st > 0; st >>= 1) {
        if (t < st) { rs[t] += rs[t + st]; rq[t] += rq[t + st]; }
        __syncthreads();
    }
    if (t == 0) { g_part[blk * 2] = rs[0]; g_part[blk * 2 + 1] = rq[0]; }
}

// ================= Fused GroupNorm-apply + QKV GEMM =================
#define QKV_SMEM (65536 + 2*32768 + 256)

__global__ __launch_bounds__(256, 1) void qkv_tc(const float* __restrict__ x,
                                                 const float* __restrict__ gamma,
                                                 const float* __restrict__ beta,
                                                 const __nv_bfloat16* __restrict__ Wh,
                                                 const float* __restrict__ bq,
                                                 const float* __restrict__ bk,
                                                 const float* __restrict__ bv,
                                                 __nv_bfloat16* __restrict__ q,
                                                 __nv_bfloat16* __restrict__ k,
                                                 __nv_bfloat16* __restrict__ v) {
    extern __shared__ char smem[];
    uint32_t sb = smem_to_u32(smem);
    const uint32_t swb = sb + 65536;
    float* sm_stat = (float*)(smem + 131072);   // mean[8], rstd[8]
    int t = threadIdx.x, lane = t & 31, warp = t >> 5;
    int m0 = blockIdx.x * 128;
    int batch = blockIdx.x >> 5;
    int wm = warp >> 2, wn = warp & 3;

#pragma unroll
    for (int i = 0; i < 8; i++) {
        int g = t + 256 * i;
        int row = g >> 5, j = g & 31;
        int j2 = (j & ~7) | ((j & 7) ^ (row & 7));
        CP_ASYNC16(swb + row * 512 + j2 * 16, Wh + (size_t)row * 256 + j * 8);
    }
    CP_COMMIT();

    if (t < 8) {
        int bg = batch * 8 + t;
        float s = 0.f, ss = 0.f;
#pragma unroll
        for (int i = 0; i < 8; i++) {
            s  += g_part[(bg * 8 + i) * 2];
            ss += g_part[(bg * 8 + i) * 2 + 1];
        }
        float mean = s * (1.f / 131072.f);
        float var  = ss * (1.f / 131072.f) - mean * mean;
        sm_stat[t] = mean;
        sm_stat[8 + t] = rsqrtf(var + 1e-3f);
    }
    __syncthreads();

    const float4* xg = (const float4*)(x + (size_t)m0 * 256);
    const float4* ga4 = (const float4*)gamma;
    const float4* be4 = (const float4*)beta;
#pragma unroll
    for (int i = 0; i < 32; i++) {
        int idx = t + 256 * i;
        int row = idx >> 6, c4 = idx & 63;
        int g = c4 >> 3;
        float mean = sm_stat[g], rstd = sm_stat[8 + g];
        float4 xv = xg[idx];
        float4 ga = ga4[c4], be = be4[c4];
        float o0 = (xv.x - mean) * rstd * ga.x + be.x;
        float o1 = (xv.y - mean) * rstd * ga.y + be.y;
        float o2 = (xv.z - mean) * rstd * ga.z + be.z;
        float o3 = (xv.w - mean) * rstd * ga.w + be.w;
        uint32_t p0, p1;
        asm("cvt.rn.satfinite.bf16x2.f32 %0, %1, %2;" : "=r"(p0) : "f"(o1), "f"(o0));
        asm("cvt.rn.satfinite.bf16x2.f32 %0, %1, %2;" : "=r"(p1) : "f"(o3), "f"(o2));
        int j = c4 >> 1;
        int j2 = (j & ~7) | ((j & 7) ^ (row & 7));
        *(uint2*)(smem + (row * 512 + j2 * 16 + (c4 & 1) * 8)) = make_uint2(p0, p1);
    }

    const int lrow = lane & 15;
    const int lsel = lane >> 4;
    const int xsw  = lrow & 7;
    const int gid  = lane >> 2, tig = lane & 3;

    float acc[4][8][4];
#pragma unroll
    for (int mt = 0; mt < 4; mt++)
#pragma unroll
        for (int nt = 0; nt < 8; nt++)
#pragma unroll
            for (int e = 0; e < 4; e++) acc[mt][nt][e] = 0.f;

    for (int p = 0; p < 12; p++) {
        if (p < 11) {
            uint32_t dst = swb + ((p + 1) & 1) * 32768;
#pragma unroll
            for (int i = 0; i < 8; i++) {
                int g = t + 256 * i;
                int row = g >> 5, j = g & 31;
                int j2 = (j & ~7) | ((j & 7) ^ (row & 7));
                CP_ASYNC16(dst + row * 512 + j2 * 16,
                           Wh + (size_t)((p + 1) * 64 + row) * 256 + j * 8);
            }
            CP_COMMIT();
            CP_WAIT1();
        } else {
            CP_WAIT0();
        }
        __syncthreads();

        uint32_t wp = swb + (p & 1) * 32768;
        int kp = p & 3;
#pragma unroll
        for (int kk = 0; kk < 4; kk++) {
            int u = kp * 8 + kk * 2 + lsel;
            int us = (u & ~7) | ((u & 7) ^ xsw);
            uint32_t a[4][4];
#pragma unroll
            for (int mt = 0; mt < 4; mt++)
                ldsm_x4(a[mt], sb + (wm * 64 + mt * 16 + lrow) * 512 + us * 16);
#pragma unroll
            for (int ng = 0; ng < 4; ng++) {
                int ub = wn * 8 + ng * 2 + lsel;
                int ubs = (ub & ~7) | ((ub & 7) ^ xsw);
                uint32_t v4[4];
                ldsm_x4_t(v4, wp + (kk * 16 + lrow) * 512 + ubs * 16);
#pragma unroll
                for (int mt = 0; mt < 4; mt++) {
                    mma16816(acc[mt][2 * ng],     a[mt], v4[0], v4[1]);
                    mma16816(acc[mt][2 * ng + 1], a[mt], v4[2], v4[3]);
                }
            }
        }
        __syncthreads();

        if ((p & 3) == 3) {
            int w = p >> 2;
            const float* bw = (w == 0) ? bq : (w == 1) ? bk : bv;
            __nv_bfloat16* ow = (w == 0) ? q : (w == 1) ? k : v;
#pragma unroll
            for (int nt = 0; nt < 8; nt++) {
                int col = wn * 64 + nt * 8 + tig * 2;
                float b0 = bw[col], b1 = bw[col + 1];
#pragma unroll
                for (int mt = 0; mt < 4; mt++) {
#pragma unroll
                    for (int h = 0; h < 2; h++) {
                        int row = m0 + wm * 64 + mt * 16 + gid + 8 * h;
                        float v0 = acc[mt][nt][2 * h]     + b0;
                        float v1 = acc[mt][nt][2 * h + 1] + b1;
                        uint32_t pck;
                        asm("cvt.rn.satfinite.bf16x2.f32 %0, %1, %2;" : "=r"(pck) : "f"(v1), "f"(v0));
                        *(uint32_t*)(ow + (size_t)row * 256 + col) = pck;
                        acc[mt][nt][2 * h] = 0.f; acc[mt][nt][2 * h + 1] = 0.f;
                    }
                }
            }
        }
    }
}

// ================= Proj GEMM (+bias +residual, fp32 out) =================
#define GT_SMEM (65536 + 2*32768)

__global__ __launch_bounds__(256, 1) void gemm_tc(const __nv_bfloat16* __restrict__ A,
                                                  const __nv_bfloat16* __restrict__ Wh,
                                                  const float* __restrict__ bias,
                                                  const float* __restrict__ residual,
                                                  float* __restrict__ out) {
    extern __shared__ char smem[];
    uint32_t sb = smem_to_u32(smem);
    const uint32_t swb = sb + 65536;
    int t = threadIdx.x, lane = t & 31, warp = t >> 5;
    int m0 = blockIdx.x * 128;
    int wm = warp >> 2, wn = warp & 3;

#pragma unroll
    for (int i = 0; i < 16; i++) {
        int g = t + 256 * i;
        int row = g >> 5, j = g & 31;
        int j2 = (j & ~7) | ((j & 7) ^ (row & 7));
        CP_ASYNC16(sb + row * 512 + j2 * 16, A + (size_t)(m0 + row) * 256 + j * 8);
    }
#pragma unroll
    for (int i = 0; i < 8; i++) {
        int g = t + 256 * i;
        int row = g >> 5, j = g & 31;
        int j2 = (j & ~7) | ((j & 7) ^ (row & 7));
        CP_ASYNC16(swb + row * 512 + j2 * 16, Wh + (size_t)row * 256 + j * 8);
    }
    CP_COMMIT();

    const int lrow = lane & 15;
    const int lsel = lane >> 4;
    const int xsw  = lrow & 7;
    const int gid  = lane >> 2, tig = lane & 3;

    float acc[4][8][4];
#pragma unroll
    for (int mt = 0; mt < 4; mt++)
#pragma unroll
        for (int nt = 0; nt < 8; nt++)
#pragma unroll
            for (int e = 0; e < 4; e++) acc[mt][nt][e] = 0.f;

    for (int p = 0; p < 4; p++) {
        if (p < 3) {
            uint32_t dst = swb + ((p + 1) & 1) * 32768;
#pragma unroll
            for (int i = 0; i < 8; i++) {
                int g = t + 256 * i;
                int row = g >> 5, j = g & 31;
                int j2 = (j & ~7) | ((j & 7) ^ (row & 7));
                CP_ASYNC16(dst + row * 512 + j2 * 16,
                           Wh + (size_t)((p + 1) * 64 + row) * 256 + j * 8);
            }
            CP_COMMIT();
            CP_WAIT1();
        } else {
            CP_WAIT0();
        }
        __syncthreads();

        uint32_t wp = swb + (p & 1) * 32768;
#pragma unroll
        for (int kk = 0; kk < 4; kk++) {
            int u = p * 8 + kk * 2 + lsel;
            int us = (u & ~7) | ((u & 7) ^ xsw);
            uint32_t a[4][4];
#pragma unroll
            for (int mt = 0; mt < 4; mt++)
                ldsm_x4(a[mt], sb + (wm * 64 + mt * 16 + lrow) * 512 + us * 16);
#pragma unroll
            for (int ng = 0; ng < 4; ng++) {
                int ub = wn * 8 + ng * 2 + lsel;
                int ubs = (ub & ~7) | ((ub & 7) ^ xsw);
                uint32_t v4[4];
                ldsm_x4_t(v4, wp + (kk * 16 + lrow) * 512 + ubs * 16);
#pragma unroll
                for (int mt = 0; mt < 4; mt++) {
                    mma16816(acc[mt][2 * ng],     a[mt], v4[0], v4[1]);
                    mma16816(acc[mt][2 * ng + 1], a[mt], v4[2], v4[3]);
                }
            }
        }
        __syncthreads();
    }

#pragma unroll
    for (int nt = 0; nt < 8; nt++) {
        int col = wn * 64 + nt * 8 + tig * 2;
        float b0 = bias[col], b1 = bias[col + 1];
#pragma unroll
        for (int mt = 0; mt < 4; mt++) {
#pragma unroll
            for (int h = 0; h < 2; h++) {
                int row = m0 + wm * 64 + mt * 16 + gid + 8 * h;
                size_t off = (size_t)row * 256 + col;
                float2 rr = *(const float2*)(residual + off);
                *(float2*)(out + off) = make_float2(acc[mt][nt][2 * h] + b0 + rr.x,
                                                    acc[mt][nt][2 * h + 1] + b1 + rr.y);
            }
        }
    }
}

// ================= Flash attention: exp interleaved under mma, 1 barrier/tile =================
// 256 thr, 8 warps x 16 Q rows, P in registers. 64-key tiles, 2 buffers.
#define FL_SMEM (192*1024)
#define EX2C 0.09016844f   // 0.0625 * log2(e)

__device__ __forceinline__ void load_kv(uint32_t sdst, const __nv_bfloat16* Kt,
                                        const __nv_bfloat16* Vt, int t) {
#pragma unroll
    for (int i = 0; i < 8; i++) {
        int g = t + 256 * i;
        int row = g >> 5, j = g & 31;
        int j2 = (j & ~7) | ((j & 7) ^ (row & 7));
        CP_ASYNC16(sdst + row * 512 + j2 * 16, Kt + row * 256 + j * 8);
        CP_ASYNC16(sdst + 32768 + row * 512 + j2 * 16, Vt + row * 256 + j * 8);
    }
}

__global__ __launch_bounds__(256, 1) void flash_mma(const __nv_bfloat16* __restrict__ Qh,
                                                    const __nv_bfloat16* __restrict__ Kh,
                                                    const __nv_bfloat16* __restrict__ Vh,
                                                    __nv_bfloat16* __restrict__ Oh) {
    extern __shared__ char smem[];
    uint32_t sb = smem_to_u32(smem);
    int t = threadIdx.x, lane = t & 31, warp = t >> 5;
    int b = blockIdx.y, qt = blockIdx.x;

    const __nv_bfloat16* Qg = Qh + ((size_t)b * NHW + qt * 128) * NC;
    const __nv_bfloat16* Kb = Kh + (size_t)b * NHW * NC;
    const __nv_bfloat16* Vb = Vh + (size_t)b * NHW * NC;

    // prologue: Q tile + KV tile 0 in one group
#pragma unroll
    for (int i = 0; i < 16; i++) {
        int g = t + 256 * i;
        int row = g >> 5, j = g & 31;
        int j2 = (j & ~7) | ((j & 7) ^ (row & 7));
        CP_ASYNC16(sb + row * 512 + j2 * 16, Qg + row * 256 + j * 8);
    }
    load_kv(sb + 65536, Kb, Vb, t);
    CP_COMMIT();

    const int lrow = lane & 15;
    const int lsel = lane >> 4;
    const int xsw  = lrow & 7;
    const uint32_t qrow = sb + (warp * 16 + lrow) * 512;

    float o[32][4];
#pragma unroll
    for (int nt = 0; nt < 32; nt++)
#pragma unroll
        for (int e = 0; e < 4; e++) o[nt][e] = 0.f;
    float l0 = 0.f, l1 = 0.f;

    for (int kt = 0; kt < 64; kt++) {
        CP_WAIT0();          // tile kt resident (issued last iter / prologue)
        __syncthreads();     // visibility + all warps done reading buf (kt+1)&1
        if (kt < 63) {       // prefetch tile kt+1 into the other buffer
            load_kv(sb + 65536 + ((kt + 1) & 1) * 65536,
                    Kb + (size_t)(kt + 1) * 64 * NC, Vb + (size_t)(kt + 1) * 64 * NC, t);
            CP_COMMIT();
        }

        uint32_t kvb = sb + 65536 + (kt & 1) * 65536;
        float s[8][4];
        uint32_t pa[4][4];
        float e0, e1, e2, e3;
        uint32_t p01, p23;

        // ---- Phase A: S half0 (keys 0-31) ----
#pragma unroll
        for (int j = 0; j < 4; j++)
#pragma unroll
            for (int e = 0; e < 4; e++) s[j][e] = 0.f;
#pragma unroll
        for (int kc = 0; kc < 16; kc++) {
            int u = kc * 2 + lsel;
            int us = (u & ~7) | ((u & 7) ^ xsw);
            uint32_t a[4], kb0[4], kb1[4];
            ldsm_x4(a, qrow + us * 16);
            ldsm_x4(kb0, kvb + lrow * 512 + us * 16);
            ldsm_x4(kb1, kvb + (16 + lrow) * 512 + us * 16);
            mma16816(s[0], a, kb0[0], kb0[2]);
            mma16816(s[1], a, kb0[1], kb0[3]);
            mma16816(s[2], a, kb1[0], kb1[2]);
            mma16816(s[3], a, kb1[1], kb1[3]);
        }

        // ---- Phase B: S half1 (keys 32-63) with exp(half0) interleaved ----
#pragma unroll
        for (int j = 4; j < 8; j++)
#pragma unroll
            for (int e = 0; e < 4; e++) s[j][e] = 0.f;
#pragma unroll
        for (int kc = 0; kc < 16; kc++) {
            int u = kc * 2 + lsel;
            int us = (u & ~7) | ((u & 7) ^ xsw);
            uint32_t a[4], kb0[4], kb1[4];
            ldsm_x4(a, qrow + us * 16);
            ldsm_x4(kb0, kvb + (32 + lrow) * 512 + us * 16);
            ldsm_x4(kb1, kvb + (48 + lrow) * 512 + us * 16);
            mma16816(s[4], a, kb0[0], kb0[2]);
            mma16816(s[5], a, kb0[1], kb0[3]);
            mma16816(s[6], a, kb1[0], kb1[2]);
            mma16816(s[7], a, kb1[1], kb1[3]);
            if ((kc & 3) == 3) {          // one exp chunk every 4 k-steps: j = kc>>2
                int j = kc >> 2;
                e0 = ex2f(s[j][0] * EX2C);
                e1 = ex2f(s[j][1] * EX2C);
                e2 = ex2f(s[j][2] * EX2C);
                e3 = ex2f(s[j][3] * EX2C);
                l0 += e0 + e1; l1 += e2 + e3;
                asm("cvt.rn.satfinite.bf16x2.f32 %0, %1, %2;" : "=r"(p01) : "f"(e1), "f"(e0));
                asm("cvt.rn.satfinite.bf16x2.f32 %0, %1, %2;" : "=r"(p23) : "f"(e3), "f"(e2));
                pa[j >> 1][(j & 1) * 2]     = p01;
                pa[j >> 1][(j & 1) * 2 + 1] = p23;
            }
        }

        // ---- Phase C: PV kc2=0,1 with exp(half1) interleaved ----
        uint32_t vbase = kvb + 32768;
#pragma unroll
        for (int kc2 = 0; kc2 < 2; kc2++) {
            uint32_t vrow = vbase + (kc2 * 16 + lrow) * 512;
#pragma unroll
            for (int ng = 0; ng < 16; ng++) {
                int u = ng * 2 + lsel;
                int us = (u & ~7) | ((u & 7) ^ xsw);
                uint32_t v4[4];
                ldsm_x4_t(v4, vrow + us * 16);
                mma16816(o[2 * ng],     pa[kc2], v4[0], v4[1]);
                mma16816(o[2 * ng + 1], pa[kc2], v4[2], v4[3]);
                if ((ng & 7) == 7) {      // j = 4 + kc2*2 + (ng>>3)
                    int j = 4 + kc2 * 2 + (ng >> 3);
                    e0 = ex2f(s[j][0] * EX2C);
                    e1 = ex2f(s[j][1] * EX2C);
                    e2 = ex2f(s[j][2] * EX2C);
                    e3 = ex2f(s[j][3] * EX2C);
                    l0 += e0 + e1; l1 += e2 + e3;
                    asm("cvt.rn.satfinite.bf16x2.f32 %0, %1, %2;" : "=r"(p01) : "f"(e1), "f"(e0));
                    asm("cvt.rn.satfinite.bf16x2.f32 %0, %1, %2;" : "=r"(p23) : "f"(e3), "f"(e2));
                    pa[j >> 1][(j & 1) * 2]     = p01;
                    pa[j >> 1][(j & 1) * 2 + 1] = p23;
                }
            }
        }

        // ---- Phase D: PV kc2=2,3 ----
#pragma unroll
        for (int kc2 = 2; kc2 < 4; kc2++) {
            uint32_t vrow = vbase + (kc2 * 16 + lrow) * 512;
#pragma unroll
            for (int ng = 0; ng < 16; ng++) {
                int u = ng * 2 + lsel;
                int us = (u & ~7) | ((u & 7) ^ xsw);
                uint32_t v4[4];
                ldsm_x4_t(v4, vrow + us * 16);
                mma16816(o[2 * ng],     pa[kc2], v4[0], v4[1]);
                mma16816(o[2 * ng + 1], pa[kc2], v4[2], v4[3]);
            }
        }
    }

    l0 += __shfl_xor_sync(0xffffffffu, l0, 1);
    l0 += __shfl_xor_sync(0xffffffffu, l0, 2);
    l1 += __shfl_xor_sync(0xffffffffu, l1, 1);
    l1 += __shfl_xor_sync(0xffffffffu, l1, 2);
    float i0 = 1.f / l0, i1 = 1.f / l1;

    int gid = lane >> 2, tig = lane & 3;
    int row0 = qt * 128 + warp * 16 + gid;
    __nv_bfloat16* O0 = Oh + ((size_t)b * NHW + row0) * NC;
#pragma unroll
    for (int nt = 0; nt < 32; nt++) {
        uint32_t p0, p1;
        float a0 = o[nt][0] * i0, a1 = o[nt][1] * i0;
        float a2 = o[nt][2] * i1, a3 = o[nt][3] * i1;
        asm("cvt.rn.satfinite.bf16x2.f32 %0, %1, %2;" : "=r"(p0) : "f"(a1), "f"(a0));
        asm("cvt.rn.satfinite.bf16x2.f32 %0, %1, %2;" : "=r"(p1) : "f"(a3), "f"(a2));
        *(uint32_t*)(O0 + nt * 8 + tig * 2) = p0;
        *(uint32_t*)(O0 + 8 * NC + nt * 8 + tig * 2) = p1;
    }
}

// ================= launch =================
extern "C" void kernel_launch(void* const* d_in, const int* in_sizes, int n_in,
                              void* d_out, int out_size) {
    const float* x     = (const float*)d_in[0];
    const float* gamma = (const float*)d_in[1];
    const float* beta  = (const float*)d_in[2];
    const float* wq    = (const float*)d_in[3];
    const float* bq    = (const float*)d_in[4];
    const float* wk    = (const float*)d_in[5];
    const float* bk    = (const float*)d_in[6];
    const float* wv    = (const float*)d_in[7];
    const float* bv    = (const float*)d_in[8];
    const float* wp    = (const float*)d_in[9];
    const float* bp    = (const float*)d_in[10];
    float* out = (float*)d_out;

    __nv_bfloat16 *p_attnh, *p_qh, *p_kh, *p_vh, *p_wh;
    cudaGetSymbolAddress((void**)&p_attnh, g_attnh);
    cudaGetSymbolAddress((void**)&p_qh,    g_qh);
    cudaGetSymbolAddress((void**)&p_kh,    g_kh);
    cudaGetSymbolAddress((void**)&p_vh,    g_vh);
    cudaGetSymbolAddress((void**)&p_wh,    g_wh);

    cudaFuncSetAttribute(flash_mma, cudaFuncAttributeMaxDynamicSharedMemorySize, FL_SMEM);
    cudaFuncSetAttribute(qkv_tc,    cudaFuncAttributeMaxDynamicSharedMemorySize, QKV_SMEM);
    cudaFuncSetAttribute(gemm_tc,   cudaFuncAttributeMaxDynamicSharedMemorySize, GT_SMEM);

    gn_stats_convw<<<512, 256>>>(x, wq, wk, wv, wp);

    qkv_tc<<<128, 256, QKV_SMEM>>>(x, gamma, beta, p_wh, bq, bk, bv, p_qh, p_kh, p_vh);

    flash_mma<<<dim3(32, 4), 256, FL_SMEM>>>(p_qh, p_kh, p_vh, p_attnh);

    gemm_tc<<<128, 256, GT_SMEM>>>(p_attnh, p_wh + 196608, bp, x, out);
}

// round 14
// speedup vs baseline: 1.0300x; 1.0300x over previous
#include <cuda_runtime.h>
#include <cuda_bf16.h>
#include <cstdint>
#include <math.h>

#define NB 4
#define NHW 4096
#define NC 256
#define NTOK (NB*NHW)   // 16384

// ================= scratch =================
__device__ __nv_bfloat16 g_attnh[NTOK*NC];
__device__ __nv_bfloat16 g_qh[NTOK*NC];
__device__ __nv_bfloat16 g_kh[NTOK*NC];
__device__ __nv_bfloat16 g_vh[NTOK*NC];
__device__ __nv_bfloat16 g_wh[4*NC*NC];   // bf16 wq|wk|wv|wp
__device__ float g_part[512];

// ================= helpers =================
__device__ __forceinline__ uint32_t smem_to_u32(const void* p) {
    uint32_t a;
    asm("{ .reg .u64 t; cvta.to.shared.u64 t, %1; cvt.u32.u64 %0, t; }" : "=r"(a) : "l"(p));
    return a;
}
#define CP_ASYNC16(saddr, gptr) \
    asm volatile("cp.async.cg.shared.global [%0], [%1], 16;" :: "r"(saddr), "l"(gptr))
#define CP_COMMIT()  asm volatile("cp.async.commit_group;" ::: "memory")
#define CP_WAIT0()   asm volatile("cp.async.wait_group 0;" ::: "memory")
#define CP_WAIT1()   asm volatile("cp.async.wait_group 1;" ::: "memory")

__device__ __forceinline__ void ldsm_x4(uint32_t* r, uint32_t addr) {
    asm volatile("ldmatrix.sync.aligned.m8n8.x4.shared.b16 {%0,%1,%2,%3}, [%4];"
        : "=r"(r[0]), "=r"(r[1]), "=r"(r[2]), "=r"(r[3]) : "r"(addr));
}
__device__ __forceinline__ void ldsm_x4_t(uint32_t* r, uint32_t addr) {
    asm volatile("ldmatrix.sync.aligned.m8n8.x4.trans.shared.b16 {%0,%1,%2,%3}, [%4];"
        : "=r"(r[0]), "=r"(r[1]), "=r"(r[2]), "=r"(r[3]) : "r"(addr));
}
__device__ __forceinline__ void mma16816(float* d, const uint32_t* a, uint32_t b0, uint32_t b1) {
    asm volatile("mma.sync.aligned.m16n8k16.row.col.f32.bf16.bf16.f32 "
        "{%0,%1,%2,%3}, {%4,%5,%6,%7}, {%8,%9}, {%0,%1,%2,%3};"
        : "+f"(d[0]), "+f"(d[1]), "+f"(d[2]), "+f"(d[3])
        : "r"(a[0]), "r"(a[1]), "r"(a[2]), "r"(a[3]), "r"(b0), "r"(b1));
}
__device__ __forceinline__ float ex2f(float x) {
    float y;
    asm("ex2.approx.ftz.f32 %0, %1;" : "=f"(y) : "f"(x));
    return y;
}

// ================= Stage 1: GN partial sums (blocks 0-255) + weight convert (blocks 256-511) =================
__global__ __launch_bounds__(256) void gn_stats_convw(const float* __restrict__ x,
                                                      const float* __restrict__ w0,
                                                      const float* __restrict__ w1,
                                                      const float* __restrict__ w2,
                                                      const float* __restrict__ w3) {
    int blk = blockIdx.x;
    int t = threadIdx.x;
    if (blk >= 256) {
        int i = (blk - 256) * 256 + t;
        int which = i >> 14, off = i & 16383;
        const float* src = which == 0 ? w0 : which == 1 ? w1 : which == 2 ? w2 : w3;
        float4 v = ((const float4*)src)[off];
        uint32_t p0, p1;
        asm("cvt.rn.satfinite.bf16x2.f32 %0, %1, %2;" : "=r"(p0) : "f"(v.y), "f"(v.x));
        asm("cvt.rn.satfinite.bf16x2.f32 %0, %1, %2;" : "=r"(p1) : "f"(v.w), "f"(v.z));
        *(uint2*)(g_wh + (size_t)which * 65536 + off * 4) = make_uint2(p0, p1);
        return;
    }
    int bg = blk >> 3, seg = blk & 7;
    int b = bg >> 3, g = bg & 7;
    const float* xb = x + (size_t)b * NHW * NC + (size_t)(seg * 512) * NC + g * 32;
    float s = 0.f, ss = 0.f;
    for (int idx = t; idx < 4096; idx += 256) {
        int p = idx >> 3, cq = idx & 7;
        float4 v = *(const float4*)(xb + (size_t)p * NC + 4 * cq);
        s  += v.x + v.y + v.z + v.w;
        ss += v.x*v.x + v.y*v.y + v.z*v.z + v.w*v.w;
    }
    __shared__ float rs[256], rq[256];
    rs[t] = s; rq[t] = ss;
    __syncthreads();
    for (int st = 128; st > 0; st >>= 1) {
        if (t < st) { rs[t] += rs[t + st]; rq[t] += rq[t + st]; }
        __syncthreads();
    }
    if (t == 0) { g_part[blk * 2] = rs[0]; g_part[blk * 2 + 1] = rq[0]; }
}

// ================= Fused GroupNorm-apply + QKV GEMM (64-row tile, 2 CTAs/SM) =================
// A tile [64][256] bf16 (32KB) @0; W buffers @32768/@65536; stats @98304.
// 8 warps = 2Mx4N, warp tile 32x64; 12 x 64-row W panels.
#define QKV_SMEM (98304 + 256)

__global__ __launch_bounds__(256, 2) void qkv_tc(const float* __restrict__ x,
                                                 const float* __restrict__ gamma,
                                                 const float* __restrict__ beta,
                                                 const __nv_bfloat16* __restrict__ Wh,
                                                 const float* __restrict__ bq,
                                                 const float* __restrict__ bk,
                                                 const float* __restrict__ bv,
                                                 __nv_bfloat16* __restrict__ q,
                                                 __nv_bfloat16* __restrict__ k,
                                                 __nv_bfloat16* __restrict__ v) {
    extern __shared__ char smem[];
    uint32_t sb = smem_to_u32(smem);
    const uint32_t swb = sb + 32768;
    float* sm_stat = (float*)(smem + 98304);   // mean[8], rstd[8]
    int t = threadIdx.x, lane = t & 31, warp = t >> 5;
    int m0 = blockIdx.x * 64;
    int batch = blockIdx.x >> 6;
    int wm = warp >> 2, wn = warp & 3;

    // prefetch W panel 0
#pragma unroll
    for (int i = 0; i < 8; i++) {
        int g = t + 256 * i;
        int row = g >> 5, j = g & 31;
        int j2 = (j & ~7) | ((j & 7) ^ (row & 7));
        CP_ASYNC16(swb + row * 512 + j2 * 16, Wh + (size_t)row * 256 + j * 8);
    }
    CP_COMMIT();

    // stats for this batch
    if (t < 8) {
        int bg = batch * 8 + t;
        float s = 0.f, ss = 0.f;
#pragma unroll
        for (int i = 0; i < 8; i++) {
            s  += g_part[(bg * 8 + i) * 2];
            ss += g_part[(bg * 8 + i) * 2 + 1];
        }
        float mean = s * (1.f / 131072.f);
        float var  = ss * (1.f / 131072.f) - mean * mean;
        sm_stat[t] = mean;
        sm_stat[8 + t] = rsqrtf(var + 1e-3f);
    }
    __syncthreads();

    // build normalized bf16 A tile [64][256]
    const float4* xg = (const float4*)(x + (size_t)m0 * 256);
    const float4* ga4 = (const float4*)gamma;
    const float4* be4 = (const float4*)beta;
#pragma unroll
    for (int i = 0; i < 16; i++) {
        int idx = t + 256 * i;              // 4096 float4
        int row = idx >> 6, c4 = idx & 63;
        int g = c4 >> 3;
        float mean = sm_stat[g], rstd = sm_stat[8 + g];
        float4 xv = xg[idx];
        float4 ga = ga4[c4], be = be4[c4];
        float o0 = (xv.x - mean) * rstd * ga.x + be.x;
        float o1 = (xv.y - mean) * rstd * ga.y + be.y;
        float o2 = (xv.z - mean) * rstd * ga.z + be.z;
        float o3 = (xv.w - mean) * rstd * ga.w + be.w;
        uint32_t p0, p1;
        asm("cvt.rn.satfinite.bf16x2.f32 %0, %1, %2;" : "=r"(p0) : "f"(o1), "f"(o0));
        asm("cvt.rn.satfinite.bf16x2.f32 %0, %1, %2;" : "=r"(p1) : "f"(o3), "f"(o2));
        int j = c4 >> 1;
        int j2 = (j & ~7) | ((j & 7) ^ (row & 7));
        *(uint2*)(smem + (row * 512 + j2 * 16 + (c4 & 1) * 8)) = make_uint2(p0, p1);
    }

    const int lrow = lane & 15;
    const int lsel = lane >> 4;
    const int xsw  = lrow & 7;
    const int gid  = lane >> 2, tig = lane & 3;

    float acc[2][8][4];
#pragma unroll
    for (int mt = 0; mt < 2; mt++)
#pragma unroll
        for (int nt = 0; nt < 8; nt++)
#pragma unroll
            for (int e = 0; e < 4; e++) acc[mt][nt][e] = 0.f;

    for (int p = 0; p < 12; p++) {
        if (p < 11) {
            uint32_t dst = swb + ((p + 1) & 1) * 32768;
#pragma unroll
            for (int i = 0; i < 8; i++) {
                int g = t + 256 * i;
                int row = g >> 5, j = g & 31;
                int j2 = (j & ~7) | ((j & 7) ^ (row & 7));
                CP_ASYNC16(dst + row * 512 + j2 * 16,
                           Wh + (size_t)((p + 1) * 64 + row) * 256 + j * 8);
            }
            CP_COMMIT();
            CP_WAIT1();
        } else {
            CP_WAIT0();
        }
        __syncthreads();

        uint32_t wp = swb + (p & 1) * 32768;
        int kp = p & 3;
#pragma unroll
        for (int kk = 0; kk < 4; kk++) {
            int u = kp * 8 + kk * 2 + lsel;
            int us = (u & ~7) | ((u & 7) ^ xsw);
            uint32_t a[2][4];
#pragma unroll
            for (int mt = 0; mt < 2; mt++)
                ldsm_x4(a[mt], sb + (wm * 32 + mt * 16 + lrow) * 512 + us * 16);
#pragma unroll
            for (int ng = 0; ng < 4; ng++) {
                int ub = wn * 8 + ng * 2 + lsel;
                int ubs = (ub & ~7) | ((ub & 7) ^ xsw);
                uint32_t v4[4];
                ldsm_x4_t(v4, wp + (kk * 16 + lrow) * 512 + ubs * 16);
#pragma unroll
                for (int mt = 0; mt < 2; mt++) {
                    mma16816(acc[mt][2 * ng],     a[mt], v4[0], v4[1]);
                    mma16816(acc[mt][2 * ng + 1], a[mt], v4[2], v4[3]);
                }
            }
        }
        __syncthreads();

        if ((p & 3) == 3) {
            int w = p >> 2;
            const float* bw = (w == 0) ? bq : (w == 1) ? bk : bv;
            __nv_bfloat16* ow = (w == 0) ? q : (w == 1) ? k : v;
#pragma unroll
            for (int nt = 0; nt < 8; nt++) {
                int col = wn * 64 + nt * 8 + tig * 2;
                float b0 = bw[col], b1 = bw[col + 1];
#pragma unroll
                for (int mt = 0; mt < 2; mt++) {
#pragma unroll
                    for (int h = 0; h < 2; h++) {
                        int row = m0 + wm * 32 + mt * 16 + gid + 8 * h;
                        float v0 = acc[mt][nt][2 * h]     + b0;
                        float v1 = acc[mt][nt][2 * h + 1] + b1;
                        uint32_t pck;
                        asm("cvt.rn.satfinite.bf16x2.f32 %0, %1, %2;" : "=r"(pck) : "f"(v1), "f"(v0));
                        *(uint32_t*)(ow + (size_t)row * 256 + col) = pck;
                        acc[mt][nt][2 * h] = 0.f; acc[mt][nt][2 * h + 1] = 0.f;
                    }
                }
            }
        }
    }
}

// ================= Proj GEMM (64-row tile, 2 CTAs/SM, +bias +residual, fp32 out) =================
#define GT_SMEM 98304

__global__ __launch_bounds__(256, 2) void gemm_tc(const __nv_bfloat16* __restrict__ A,
                                                  const __nv_bfloat16* __restrict__ Wh,
                                                  const float* __restrict__ bias,
                                                  const float* __restrict__ residual,
                                                  float* __restrict__ out) {
    extern __shared__ char smem[];
    uint32_t sb = smem_to_u32(smem);
    const uint32_t swb = sb + 32768;
    int t = threadIdx.x, lane = t & 31, warp = t >> 5;
    int m0 = blockIdx.x * 64;
    int wm = warp >> 2, wn = warp & 3;

    // A tile [64][256] bf16 (8 x 16B per thread) + W panel 0
#pragma unroll
    for (int i = 0; i < 8; i++) {
        int g = t + 256 * i;
        int row = g >> 5, j = g & 31;
        int j2 = (j & ~7) | ((j & 7) ^ (row & 7));
        CP_ASYNC16(sb + row * 512 + j2 * 16, A + (size_t)(m0 + row) * 256 + j * 8);
    }
#pragma unroll
    for (int i = 0; i < 8; i++) {
        int g = t + 256 * i;
        int row = g >> 5, j = g & 31;
        int j2 = (j & ~7) | ((j & 7) ^ (row & 7));
        CP_ASYNC16(swb + row * 512 + j2 * 16, Wh + (size_t)row * 256 + j * 8);
    }
    CP_COMMIT();

    const int lrow = lane & 15;
    const int lsel = lane >> 4;
    const int xsw  = lrow & 7;
    const int gid  = lane >> 2, tig = lane & 3;

    float acc[2][8][4];
#pragma unroll
    for (int mt = 0; mt < 2; mt++)
#pragma unroll
        for (int nt = 0; nt < 8; nt++)
#pragma unroll
            for (int e = 0; e < 4; e++) acc[mt][nt][e] = 0.f;

    for (int p = 0; p < 4; p++) {
        if (p < 3) {
            uint32_t dst = swb + ((p + 1) & 1) * 32768;
#pragma unroll
            for (int i = 0; i < 8; i++) {
                int g = t + 256 * i;
                int row = g >> 5, j = g & 31;
                int j2 = (j & ~7) | ((j & 7) ^ (row & 7));
                CP_ASYNC16(dst + row * 512 + j2 * 16,
                           Wh + (size_t)((p + 1) * 64 + row) * 256 + j * 8);
            }
            CP_COMMIT();
            CP_WAIT1();
        } else {
            CP_WAIT0();
        }
        __syncthreads();

        uint32_t wp = swb + (p & 1) * 32768;
#pragma unroll
        for (int kk = 0; kk < 4; kk++) {
            int u = p * 8 + kk * 2 + lsel;
            int us = (u & ~7) | ((u & 7) ^ xsw);
            uint32_t a[2][4];
#pragma unroll
            for (int mt = 0; mt < 2; mt++)
                ldsm_x4(a[mt], sb + (wm * 32 + mt * 16 + lrow) * 512 + us * 16);
#pragma unroll
            for (int ng = 0; ng < 4; ng++) {
                int ub = wn * 8 + ng * 2 + lsel;
                int ubs = (ub & ~7) | ((ub & 7) ^ xsw);
                uint32_t v4[4];
                ldsm_x4_t(v4, wp + (kk * 16 + lrow) * 512 + ubs * 16);
#pragma unroll
                for (int mt = 0; mt < 2; mt++) {
                    mma16816(acc[mt][2 * ng],     a[mt], v4[0], v4[1]);
                    mma16816(acc[mt][2 * ng + 1], a[mt], v4[2], v4[3]);
                }
            }
        }
        __syncthreads();
    }

#pragma unroll
    for (int nt = 0; nt < 8; nt++) {
        int col = wn * 64 + nt * 8 + tig * 2;
        float b0 = bias[col], b1 = bias[col + 1];
#pragma unroll
        for (int mt = 0; mt < 2; mt++) {
#pragma unroll
            for (int h = 0; h < 2; h++) {
                int row = m0 + wm * 32 + mt * 16 + gid + 8 * h;
                size_t off = (size_t)row * 256 + col;
                float2 rr = *(const float2*)(residual + off);
                *(float2*)(out + off) = make_float2(acc[mt][nt][2 * h] + b0 + rr.x,
                                                    acc[mt][nt][2 * h + 1] + b1 + rr.y);
            }
        }
    }
}

// ================= Flash attention (R12-proven: 256 thr, P in registers, 2 barriers/tile) =================
#define FL_SMEM (192*1024)
#define EX2C 0.09016844f   // 0.0625 * log2(e)

__device__ __forceinline__ void load_kv(uint32_t sdst, const __nv_bfloat16* Kt,
                                        const __nv_bfloat16* Vt, int t) {
#pragma unroll
    for (int i = 0; i < 8; i++) {
        int g = t + 256 * i;
        int row = g >> 5, j = g & 31;
        int j2 = (j & ~7) | ((j & 7) ^ (row & 7));
        CP_ASYNC16(sdst + row * 512 + j2 * 16, Kt + row * 256 + j * 8);
        CP_ASYNC16(sdst + 32768 + row * 512 + j2 * 16, Vt + row * 256 + j * 8);
    }
}

__global__ __launch_bounds__(256, 1) void flash_mma(const __nv_bfloat16* __restrict__ Qh,
                                                    const __nv_bfloat16* __restrict__ Kh,
                                                    const __nv_bfloat16* __restrict__ Vh,
                                                    __nv_bfloat16* __restrict__ Oh) {
    extern __shared__ char smem[];
    uint32_t sb = smem_to_u32(smem);
    int t = threadIdx.x, lane = t & 31, warp = t >> 5;
    int b = blockIdx.y, qt = blockIdx.x;

    const __nv_bfloat16* Qg = Qh + ((size_t)b * NHW + qt * 128) * NC;
    const __nv_bfloat16* Kb = Kh + (size_t)b * NHW * NC;
    const __nv_bfloat16* Vb = Vh + (size_t)b * NHW * NC;

#pragma unroll
    for (int i = 0; i < 16; i++) {
        int g = t + 256 * i;
        int row = g >> 5, j = g & 31;
        int j2 = (j & ~7) | ((j & 7) ^ (row & 7));
        CP_ASYNC16(sb + row * 512 + j2 * 16, Qg + row * 256 + j * 8);
    }
    load_kv(sb + 65536, Kb, Vb, t);
    CP_COMMIT();

    const int lrow = lane & 15;
    const int lsel = lane >> 4;
    const int xsw  = lrow & 7;
    const uint32_t qrow = sb + (warp * 16 + lrow) * 512;

    float o[32][4];
#pragma unroll
    for (int nt = 0; nt < 32; nt++)
#pragma unroll
        for (int e = 0; e < 4; e++) o[nt][e] = 0.f;
    float l0 = 0.f, l1 = 0.f;

    for (int kt = 0; kt < 64; kt++) {
        if (kt < 63) {
            load_kv(sb + 65536 + ((kt + 1) & 1) * 65536,
                    Kb + (size_t)(kt + 1) * 64 * NC, Vb + (size_t)(kt + 1) * 64 * NC, t);
            CP_COMMIT();
            CP_WAIT1();
        } else {
            CP_WAIT0();
        }
        __syncthreads();

        uint32_t kvb = sb + 65536 + (kt & 1) * 65536;

        float s[8][4];
#pragma unroll
        for (int j = 0; j < 8; j++)
#pragma unroll
            for (int e = 0; e < 4; e++) s[j][e] = 0.f;
#pragma unroll
        for (int kc = 0; kc < 16; kc++) {
            int u = kc * 2 + lsel;
            int us = (u & ~7) | ((u & 7) ^ xsw);
            uint32_t a[4];
            ldsm_x4(a, qrow + us * 16);
#pragma unroll
            for (int g4 = 0; g4 < 4; g4++) {
                uint32_t kb[4];
                ldsm_x4(kb, kvb + (g4 * 16 + lrow) * 512 + us * 16);
                mma16816(s[2 * g4],     a, kb[0], kb[2]);
                mma16816(s[2 * g4 + 1], a, kb[1], kb[3]);
            }
        }

        uint32_t pa[4][4];
#pragma unroll
        for (int j = 0; j < 8; j++) {
            float e0 = ex2f(s[j][0] * EX2C);
            float e1 = ex2f(s[j][1] * EX2C);
            float e2 = ex2f(s[j][2] * EX2C);
            float e3 = ex2f(s[j][3] * EX2C);
            l0 += e0 + e1; l1 += e2 + e3;
            uint32_t p01, p23;
            asm("cvt.rn.satfinite.bf16x2.f32 %0, %1, %2;" : "=r"(p01) : "f"(e1), "f"(e0));
            asm("cvt.rn.satfinite.bf16x2.f32 %0, %1, %2;" : "=r"(p23) : "f"(e3), "f"(e2));
            pa[j >> 1][(j & 1) * 2]     = p01;
            pa[j >> 1][(j & 1) * 2 + 1] = p23;
        }

        uint32_t vbase = kvb + 32768;
#pragma unroll
        for (int kc2 = 0; kc2 < 4; kc2++) {
            uint32_t vrow = vbase + (kc2 * 16 + lrow) * 512;
#pragma unroll
            for (int ng = 0; ng < 16; ng++) {
                int u = ng * 2 + lsel;
                int us = (u & ~7) | ((u & 7) ^ xsw);
                uint32_t v4[4];
                ldsm_x4_t(v4, vrow + us * 16);
                mma16816(o[2 * ng],     pa[kc2], v4[0], v4[1]);
                mma16816(o[2 * ng + 1], pa[kc2], v4[2], v4[3]);
            }
        }
        __syncthreads();
    }

    l0 += __shfl_xor_sync(0xffffffffu, l0, 1);
    l0 += __shfl_xor_sync(0xffffffffu, l0, 2);
    l1 += __shfl_xor_sync(0xffffffffu, l1, 1);
    l1 += __shfl_xor_sync(0xffffffffu, l1, 2);
    float i0 = 1.f / l0, i1 = 1.f / l1;

    int gid = lane >> 2, tig = lane & 3;
    int row0 = qt * 128 + warp * 16 + gid;
    __nv_bfloat16* O0 = Oh + ((size_t)b * NHW + row0) * NC;
#pragma unroll
    for (int nt = 0; nt < 32; nt++) {
        uint32_t p0, p1;
        float a0 = o[nt][0] * i0, a1 = o[nt][1] * i0;
        float a2 = o[nt][2] * i1, a3 = o[nt][3] * i1;
        asm("cvt.rn.satfinite.bf16x2.f32 %0, %1, %2;" : "=r"(p0) : "f"(a1), "f"(a0));
        asm("cvt.rn.satfinite.bf16x2.f32 %0, %1, %2;" : "=r"(p1) : "f"(a3), "f"(a2));
        *(uint32_t*)(O0 + nt * 8 + tig * 2) = p0;
        *(uint32_t*)(O0 + 8 * NC + nt * 8 + tig * 2) = p1;
    }
}

// ================= launch =================
extern "C" void kernel_launch(void* const* d_in, const int* in_sizes, int n_in,
                              void* d_out, int out_size) {
    const float* x     = (const float*)d_in[0];
    const float* gamma = (const float*)d_in[1];
    const float* beta  = (const float*)d_in[2];
    const float* wq    = (const float*)d_in[3];
    const float* bq    = (const float*)d_in[4];
    const float* wk    = (const float*)d_in[5];
    const float* bk    = (const float*)d_in[6];
    const float* wv    = (const float*)d_in[7];
    const float* bv    = (const float*)d_in[8];
    const float* wp    = (const float*)d_in[9];
    const float* bp    = (const float*)d_in[10];
    float* out = (float*)d_out;

    __nv_bfloat16 *p_attnh, *p_qh, *p_kh, *p_vh, *p_wh;
    cudaGetSymbolAddress((void**)&p_attnh, g_attnh);
    cudaGetSymbolAddress((void**)&p_qh,    g_qh);
    cudaGetSymbolAddress((void**)&p_kh,    g_kh);
    cudaGetSymbolAddress((void**)&p_vh,    g_vh);
    cudaGetSymbolAddress((void**)&p_wh,    g_wh);

    cudaFuncSetAttribute(flash_mma, cudaFuncAttributeMaxDynamicSharedMemorySize, FL_SMEM);
    cudaFuncSetAttribute(qkv_tc,    cudaFuncAttributeMaxDynamicSharedMemorySize, QKV_SMEM);
    cudaFuncSetAttribute(gemm_tc,   cudaFuncAttributeMaxDynamicSharedMemorySize, GT_SMEM);

    gn_stats_convw<<<512, 256>>>(x, wq, wk, wv, wp);

    qkv_tc<<<256, 256, QKV_SMEM>>>(x, gamma, beta, p_wh, bq, bk, bv, p_qh, p_kh, p_vh);

    flash_mma<<<dim3(32, 4), 256, FL_SMEM>>>(p_qh, p_kh, p_vh, p_attnh);

    gemm_tc<<<256, 256, GT_SMEM>>>(p_attnh, p_wh + 196608, bp, x, out);
}

// round 15
// speedup vs baseline: 1.0424x; 1.0121x over previous
#include <cuda_runtime.h>
#include <cuda_bf16.h>
#include <cstdint>
#include <math.h>

#define NB 4
#define NHW 4096
#define NC 256
#define NTOK (NB*NHW)   // 16384

// ================= scratch =================
__device__ __nv_bfloat16 g_qh[NTOK*NC];
__device__ __nv_bfloat16 g_kh[NTOK*NC];
__device__ __nv_bfloat16 g_vh[NTOK*NC];
__device__ __nv_bfloat16 g_wh[4*NC*NC];   // bf16 wq|wk|wv|wp
__device__ float g_part[512];

// ================= helpers =================
__device__ __forceinline__ uint32_t smem_to_u32(const void* p) {
    uint32_t a;
    asm("{ .reg .u64 t; cvta.to.shared.u64 t, %1; cvt.u32.u64 %0, t; }" : "=r"(a) : "l"(p));
    return a;
}
#define CP_ASYNC16(saddr, gptr) \
    asm volatile("cp.async.cg.shared.global [%0], [%1], 16;" :: "r"(saddr), "l"(gptr))
#define CP_COMMIT()  asm volatile("cp.async.commit_group;" ::: "memory")
#define CP_WAIT0()   asm volatile("cp.async.wait_group 0;" ::: "memory")
#define CP_WAIT1()   asm volatile("cp.async.wait_group 1;" ::: "memory")

__device__ __forceinline__ void ldsm_x4(uint32_t* r, uint32_t addr) {
    asm volatile("ldmatrix.sync.aligned.m8n8.x4.shared.b16 {%0,%1,%2,%3}, [%4];"
        : "=r"(r[0]), "=r"(r[1]), "=r"(r[2]), "=r"(r[3]) : "r"(addr));
}
__device__ __forceinline__ void ldsm_x4_t(uint32_t* r, uint32_t addr) {
    asm volatile("ldmatrix.sync.aligned.m8n8.x4.trans.shared.b16 {%0,%1,%2,%3}, [%4];"
        : "=r"(r[0]), "=r"(r[1]), "=r"(r[2]), "=r"(r[3]) : "r"(addr));
}
__device__ __forceinline__ void mma16816(float* d, const uint32_t* a, uint32_t b0, uint32_t b1) {
    asm volatile("mma.sync.aligned.m16n8k16.row.col.f32.bf16.bf16.f32 "
        "{%0,%1,%2,%3}, {%4,%5,%6,%7}, {%8,%9}, {%0,%1,%2,%3};"
        : "+f"(d[0]), "+f"(d[1]), "+f"(d[2]), "+f"(d[3])
        : "r"(a[0]), "r"(a[1]), "r"(a[2]), "r"(a[3]), "r"(b0), "r"(b1));
}
__device__ __forceinline__ float ex2f(float x) {
    float y;
    asm("ex2.approx.ftz.f32 %0, %1;" : "=f"(y) : "f"(x));
    return y;
}

// ================= Stage 1: GN partial sums (blocks 0-255) + weight convert (blocks 256-511) =================
__global__ __launch_bounds__(256) void gn_stats_convw(const float* __restrict__ x,
                                                      const float* __restrict__ w0,
                                                      const float* __restrict__ w1,
                                                      const float* __restrict__ w2,
                                                      const float* __restrict__ w3) {
    int blk = blockIdx.x;
    int t = threadIdx.x;
    if (blk >= 256) {
        int i = (blk - 256) * 256 + t;
        int which = i >> 14, off = i & 16383;
        const float* src = which == 0 ? w0 : which == 1 ? w1 : which == 2 ? w2 : w3;
        float4 v = ((const float4*)src)[off];
        uint32_t p0, p1;
        asm("cvt.rn.satfinite.bf16x2.f32 %0, %1, %2;" : "=r"(p0) : "f"(v.y), "f"(v.x));
        asm("cvt.rn.satfinite.bf16x2.f32 %0, %1, %2;" : "=r"(p1) : "f"(v.w), "f"(v.z));
        *(uint2*)(g_wh + (size_t)which * 65536 + off * 4) = make_uint2(p0, p1);
        return;
    }
    int bg = blk >> 3, seg = blk & 7;
    int b = bg >> 3, g = bg & 7;
    const float* xb = x + (size_t)b * NHW * NC + (size_t)(seg * 512) * NC + g * 32;
    float s = 0.f, ss = 0.f;
    for (int idx = t; idx < 4096; idx += 256) {
        int p = idx >> 3, cq = idx & 7;
        float4 v = *(const float4*)(xb + (size_t)p * NC + 4 * cq);
        s  += v.x + v.y + v.z + v.w;
        ss += v.x*v.x + v.y*v.y + v.z*v.z + v.w*v.w;
    }
    __shared__ float rs[256], rq[256];
    rs[t] = s; rq[t] = ss;
    __syncthreads();
    for (int st = 128; st > 0; st >>= 1) {
        if (t < st) { rs[t] += rs[t + st]; rq[t] += rq[t + st]; }
        __syncthreads();
    }
    if (t == 0) { g_part[blk * 2] = rs[0]; g_part[blk * 2 + 1] = rq[0]; }
}

// ================= Fused GroupNorm-apply + QKV GEMM (R12-proven, 128-row tile) =================
#define QKV_SMEM (65536 + 2*32768 + 256)

__global__ __launch_bounds__(256, 1) void qkv_tc(const float* __restrict__ x,
                                                 const float* __restrict__ gamma,
                                                 const float* __restrict__ beta,
                                                 const __nv_bfloat16* __restrict__ Wh,
                                                 const float* __restrict__ bq,
                                                 const float* __restrict__ bk,
                                                 const float* __restrict__ bv,
                                                 __nv_bfloat16* __restrict__ q,
                                                 __nv_bfloat16* __restrict__ k,
                                                 __nv_bfloat16* __restrict__ v) {
    extern __shared__ char smem[];
    uint32_t sb = smem_to_u32(smem);
    const uint32_t swb = sb + 65536;
    float* sm_stat = (float*)(smem + 131072);
    int t = threadIdx.x, lane = t & 31, warp = t >> 5;
    int m0 = blockIdx.x * 128;
    int batch = blockIdx.x >> 5;
    int wm = warp >> 2, wn = warp & 3;

#pragma unroll
    for (int i = 0; i < 8; i++) {
        int g = t + 256 * i;
        int row = g >> 5, j = g & 31;
        int j2 = (j & ~7) | ((j & 7) ^ (row & 7));
        CP_ASYNC16(swb + row * 512 + j2 * 16, Wh + (size_t)row * 256 + j * 8);
    }
    CP_COMMIT();

    if (t < 8) {
        int bg = batch * 8 + t;
        float s = 0.f, ss = 0.f;
#pragma unroll
        for (int i = 0; i < 8; i++) {
            s  += g_part[(bg * 8 + i) * 2];
            ss += g_part[(bg * 8 + i) * 2 + 1];
        }
        float mean = s * (1.f / 131072.f);
        float var  = ss * (1.f / 131072.f) - mean * mean;
        sm_stat[t] = mean;
        sm_stat[8 + t] = rsqrtf(var + 1e-3f);
    }
    __syncthreads();

    const float4* xg = (const float4*)(x + (size_t)m0 * 256);
    const float4* ga4 = (const float4*)gamma;
    const float4* be4 = (const float4*)beta;
#pragma unroll
    for (int i = 0; i < 32; i++) {
        int idx = t + 256 * i;
        int row = idx >> 6, c4 = idx & 63;
        int g = c4 >> 3;
        float mean = sm_stat[g], rstd = sm_stat[8 + g];
        float4 xv = xg[idx];
        float4 ga = ga4[c4], be = be4[c4];
        float o0 = (xv.x - mean) * rstd * ga.x + be.x;
        float o1 = (xv.y - mean) * rstd * ga.y + be.y;
        float o2 = (xv.z - mean) * rstd * ga.z + be.z;
        float o3 = (xv.w - mean) * rstd * ga.w + be.w;
        uint32_t p0, p1;
        asm("cvt.rn.satfinite.bf16x2.f32 %0, %1, %2;" : "=r"(p0) : "f"(o1), "f"(o0));
        asm("cvt.rn.satfinite.bf16x2.f32 %0, %1, %2;" : "=r"(p1) : "f"(o3), "f"(o2));
        int j = c4 >> 1;
        int j2 = (j & ~7) | ((j & 7) ^ (row & 7));
        *(uint2*)(smem + (row * 512 + j2 * 16 + (c4 & 1) * 8)) = make_uint2(p0, p1);
    }

    const int lrow = lane & 15;
    const int lsel = lane >> 4;
    const int xsw  = lrow & 7;
    const int gid  = lane >> 2, tig = lane & 3;

    float acc[4][8][4];
#pragma unroll
    for (int mt = 0; mt < 4; mt++)
#pragma unroll
        for (int nt = 0; nt < 8; nt++)
#pragma unroll
            for (int e = 0; e < 4; e++) acc[mt][nt][e] = 0.f;

    for (int p = 0; p < 12; p++) {
        if (p < 11) {
            uint32_t dst = swb + ((p + 1) & 1) * 32768;
#pragma unroll
            for (int i = 0; i < 8; i++) {
                int g = t + 256 * i;
                int row = g >> 5, j = g & 31;
                int j2 = (j & ~7) | ((j & 7) ^ (row & 7));
                CP_ASYNC16(dst + row * 512 + j2 * 16,
                           Wh + (size_t)((p + 1) * 64 + row) * 256 + j * 8);
            }
            CP_COMMIT();
            CP_WAIT1();
        } else {
            CP_WAIT0();
        }
        __syncthreads();

        uint32_t wp = swb + (p & 1) * 32768;
        int kp = p & 3;
#pragma unroll
        for (int kk = 0; kk < 4; kk++) {
            int u = kp * 8 + kk * 2 + lsel;
            int us = (u & ~7) | ((u & 7) ^ xsw);
            uint32_t a[4][4];
#pragma unroll
            for (int mt = 0; mt < 4; mt++)
                ldsm_x4(a[mt], sb + (wm * 64 + mt * 16 + lrow) * 512 + us * 16);
#pragma unroll
            for (int ng = 0; ng < 4; ng++) {
                int ub = wn * 8 + ng * 2 + lsel;
                int ubs = (ub & ~7) | ((ub & 7) ^ xsw);
                uint32_t v4[4];
                ldsm_x4_t(v4, wp + (kk * 16 + lrow) * 512 + ubs * 16);
#pragma unroll
                for (int mt = 0; mt < 4; mt++) {
                    mma16816(acc[mt][2 * ng],     a[mt], v4[0], v4[1]);
                    mma16816(acc[mt][2 * ng + 1], a[mt], v4[2], v4[3]);
                }
            }
        }
        __syncthreads();

        if ((p & 3) == 3) {
            int w = p >> 2;
            const float* bw = (w == 0) ? bq : (w == 1) ? bk : bv;
            __nv_bfloat16* ow = (w == 0) ? q : (w == 1) ? k : v;
#pragma unroll
            for (int nt = 0; nt < 8; nt++) {
                int col = wn * 64 + nt * 8 + tig * 2;
                float b0 = bw[col], b1 = bw[col + 1];
#pragma unroll
                for (int mt = 0; mt < 4; mt++) {
#pragma unroll
                    for (int h = 0; h < 2; h++) {
                        int row = m0 + wm * 64 + mt * 16 + gid + 8 * h;
                        float v0 = acc[mt][nt][2 * h]     + b0;
                        float v1 = acc[mt][nt][2 * h + 1] + b1;
                        uint32_t pck;
                        asm("cvt.rn.satfinite.bf16x2.f32 %0, %1, %2;" : "=r"(pck) : "f"(v1), "f"(v0));
                        *(uint32_t*)(ow + (size_t)row * 256 + col) = pck;
                        acc[mt][nt][2 * h] = 0.f; acc[mt][nt][2 * h + 1] = 0.f;
                    }
                }
            }
        }
    }
}

// ================= Flash attention + fused proj epilogue =================
// Main KV loop is byte-identical to R12. After the loop:
//   stage O/l as bf16 A-tile in dead KV smem, stream wp panels through dead Q smem,
//   run the proj GEMM in-place, write out = acc + bp + x.
#define FL_SMEM (192*1024)
#define EX2C 0.09016844f   // 0.0625 * log2(e)

__device__ __forceinline__ void load_kv(uint32_t sdst, const __nv_bfloat16* Kt,
                                        const __nv_bfloat16* Vt, int t) {
#pragma unroll
    for (int i = 0; i < 8; i++) {
        int g = t + 256 * i;
        int row = g >> 5, j = g & 31;
        int j2 = (j & ~7) | ((j & 7) ^ (row & 7));
        CP_ASYNC16(sdst + row * 512 + j2 * 16, Kt + row * 256 + j * 8);
        CP_ASYNC16(sdst + 32768 + row * 512 + j2 * 16, Vt + row * 256 + j * 8);
    }
}

__global__ __launch_bounds__(256, 1) void flash_mma(const __nv_bfloat16* __restrict__ Qh,
                                                    const __nv_bfloat16* __restrict__ Kh,
                                                    const __nv_bfloat16* __restrict__ Vh,
                                                    const __nv_bfloat16* __restrict__ Wp,
                                                    const float* __restrict__ bp,
                                                    const float* __restrict__ xres,
                                                    float* __restrict__ out) {
    extern __shared__ char smem[];
    uint32_t sb = smem_to_u32(smem);
    int t = threadIdx.x, lane = t & 31, warp = t >> 5;
    int b = blockIdx.y, qt = blockIdx.x;

    const __nv_bfloat16* Qg = Qh + ((size_t)b * NHW + qt * 128) * NC;
    const __nv_bfloat16* Kb = Kh + (size_t)b * NHW * NC;
    const __nv_bfloat16* Vb = Vh + (size_t)b * NHW * NC;

#pragma unroll
    for (int i = 0; i < 16; i++) {
        int g = t + 256 * i;
        int row = g >> 5, j = g & 31;
        int j2 = (j & ~7) | ((j & 7) ^ (row & 7));
        CP_ASYNC16(sb + row * 512 + j2 * 16, Qg + row * 256 + j * 8);
    }
    load_kv(sb + 65536, Kb, Vb, t);
    CP_COMMIT();

    const int lrow = lane & 15;
    const int lsel = lane >> 4;
    const int xsw  = lrow & 7;
    const uint32_t qrow = sb + (warp * 16 + lrow) * 512;

    float o[32][4];
#pragma unroll
    for (int nt = 0; nt < 32; nt++)
#pragma unroll
        for (int e = 0; e < 4; e++) o[nt][e] = 0.f;
    float l0 = 0.f, l1 = 0.f;

    for (int kt = 0; kt < 64; kt++) {
        if (kt < 63) {
            load_kv(sb + 65536 + ((kt + 1) & 1) * 65536,
                    Kb + (size_t)(kt + 1) * 64 * NC, Vb + (size_t)(kt + 1) * 64 * NC, t);
            CP_COMMIT();
            CP_WAIT1();
        } else {
            CP_WAIT0();
        }
        __syncthreads();

        uint32_t kvb = sb + 65536 + (kt & 1) * 65536;

        float s[8][4];
#pragma unroll
        for (int j = 0; j < 8; j++)
#pragma unroll
            for (int e = 0; e < 4; e++) s[j][e] = 0.f;
#pragma unroll
        for (int kc = 0; kc < 16; kc++) {
            int u = kc * 2 + lsel;
            int us = (u & ~7) | ((u & 7) ^ xsw);
            uint32_t a[4];
            ldsm_x4(a, qrow + us * 16);
#pragma unroll
            for (int g4 = 0; g4 < 4; g4++) {
                uint32_t kb[4];
                ldsm_x4(kb, kvb + (g4 * 16 + lrow) * 512 + us * 16);
                mma16816(s[2 * g4],     a, kb[0], kb[2]);
                mma16816(s[2 * g4 + 1], a, kb[1], kb[3]);
            }
        }

        uint32_t pa[4][4];
#pragma unroll
        for (int j = 0; j < 8; j++) {
            float e0 = ex2f(s[j][0] * EX2C);
            float e1 = ex2f(s[j][1] * EX2C);
            float e2 = ex2f(s[j][2] * EX2C);
            float e3 = ex2f(s[j][3] * EX2C);
            l0 += e0 + e1; l1 += e2 + e3;
            uint32_t p01, p23;
            asm("cvt.rn.satfinite.bf16x2.f32 %0, %1, %2;" : "=r"(p01) : "f"(e1), "f"(e0));
            asm("cvt.rn.satfinite.bf16x2.f32 %0, %1, %2;" : "=r"(p23) : "f"(e3), "f"(e2));
            pa[j >> 1][(j & 1) * 2]     = p01;
            pa[j >> 1][(j & 1) * 2 + 1] = p23;
        }

        uint32_t vbase = kvb + 32768;
#pragma unroll
        for (int kc2 = 0; kc2 < 4; kc2++) {
            uint32_t vrow = vbase + (kc2 * 16 + lrow) * 512;
#pragma unroll
            for (int ng = 0; ng < 16; ng++) {
                int u = ng * 2 + lsel;
                int us = (u & ~7) | ((u & 7) ^ xsw);
                uint32_t v4[4];
                ldsm_x4_t(v4, vrow + us * 16);
                mma16816(o[2 * ng],     pa[kc2], v4[0], v4[1]);
                mma16816(o[2 * ng + 1], pa[kc2], v4[2], v4[3]);
            }
        }
        __syncthreads();
    }

    // ---- l reduction ----
    l0 += __shfl_xor_sync(0xffffffffu, l0, 1);
    l0 += __shfl_xor_sync(0xffffffffu, l0, 2);
    l1 += __shfl_xor_sync(0xffffffffu, l1, 1);
    l1 += __shfl_xor_sync(0xffffffffu, l1, 2);
    float i0 = 1.f / l0, i1 = 1.f / l1;

    const int gid = lane >> 2, tig = lane & 3;

    // ---- prefetch proj W panel 0 into dead Q region (Q smem no longer read) ----
#pragma unroll
    for (int i = 0; i < 8; i++) {
        int g = t + 256 * i;
        int row = g >> 5, j = g & 31;
        int j2 = (j & ~7) | ((j & 7) ^ (row & 7));
        CP_ASYNC16(sb + row * 512 + j2 * 16, Wp + (size_t)row * 256 + j * 8);
    }
    CP_COMMIT();

    // ---- stage normalized O as swizzled bf16 A-tile in dead KV region (@ +65536) ----
    const uint32_t Ab = sb + 65536;
    {
        int row0 = warp * 16 + gid;
        int row1 = row0 + 8;
#pragma unroll
        for (int nt = 0; nt < 32; nt++) {
            uint32_t p0, p1;
            float a0 = o[nt][0] * i0, a1 = o[nt][1] * i0;
            float a2 = o[nt][2] * i1, a3 = o[nt][3] * i1;
            asm("cvt.rn.satfinite.bf16x2.f32 %0, %1, %2;" : "=r"(p0) : "f"(a1), "f"(a0));
            asm("cvt.rn.satfinite.bf16x2.f32 %0, %1, %2;" : "=r"(p1) : "f"(a3), "f"(a2));
            int u2 = (nt & ~7) | ((nt & 7) ^ (row0 & 7));   // (row1&7)==(row0&7)
            asm volatile("st.shared.b32 [%0], %1;" :: "r"(Ab + row0 * 512 + u2 * 16 + tig * 4), "r"(p0) : "memory");
            asm volatile("st.shared.b32 [%0], %1;" :: "r"(Ab + row1 * 512 + u2 * 16 + tig * 4), "r"(p1) : "memory");
        }
    }
    __syncthreads();

    // ---- proj GEMM: out_tile[128,256] = A[128,256] @ Wp + bp + x ----
    int wm = warp >> 2, wn = warp & 3;
    float acc[4][8][4];
#pragma unroll
    for (int mt = 0; mt < 4; mt++)
#pragma unroll
        for (int nt = 0; nt < 8; nt++)
#pragma unroll
            for (int e = 0; e < 4; e++) acc[mt][nt][e] = 0.f;

    for (int p = 0; p < 4; p++) {
        if (p < 3) {
            uint32_t dst = sb + ((p + 1) & 1) * 32768;
#pragma unroll
            for (int i = 0; i < 8; i++) {
                int g = t + 256 * i;
                int row = g >> 5, j = g & 31;
                int j2 = (j & ~7) | ((j & 7) ^ (row & 7));
                CP_ASYNC16(dst + row * 512 + j2 * 16,
                           Wp + (size_t)((p + 1) * 64 + row) * 256 + j * 8);
            }
            CP_COMMIT();
            CP_WAIT1();
        } else {
            CP_WAIT0();
        }
        __syncthreads();

        uint32_t wpp = sb + (p & 1) * 32768;
#pragma unroll
        for (int kk = 0; kk < 4; kk++) {
            int u = p * 8 + kk * 2 + lsel;
            int us = (u & ~7) | ((u & 7) ^ xsw);
            uint32_t a[4][4];
#pragma unroll
            for (int mt = 0; mt < 4; mt++)
                ldsm_x4(a[mt], Ab + (wm * 64 + mt * 16 + lrow) * 512 + us * 16);
#pragma unroll
            for (int ng = 0; ng < 4; ng++) {
                int ub = wn * 8 + ng * 2 + lsel;
                int ubs = (ub & ~7) | ((ub & 7) ^ xsw);
                uint32_t v4[4];
                ldsm_x4_t(v4, wpp + (kk * 16 + lrow) * 512 + ubs * 16);
#pragma unroll
                for (int mt = 0; mt < 4; mt++) {
                    mma16816(acc[mt][2 * ng],     a[mt], v4[0], v4[1]);
                    mma16816(acc[mt][2 * ng + 1], a[mt], v4[2], v4[3]);
                }
            }
        }
        __syncthreads();
    }

    // ---- final epilogue: out = acc + bp + x ----
    size_t base = ((size_t)b * NHW + qt * 128);
#pragma unroll
    for (int nt = 0; nt < 8; nt++) {
        int col = wn * 64 + nt * 8 + tig * 2;
        float b0 = bp[col], b1 = bp[col + 1];
#pragma unroll
        for (int mt = 0; mt < 4; mt++) {
#pragma unroll
            for (int h = 0; h < 2; h++) {
                int row = wm * 64 + mt * 16 + gid + 8 * h;
                size_t off = (base + row) * 256 + col;
                float2 rr = *(const float2*)(xres + off);
                *(float2*)(out + off) = make_float2(acc[mt][nt][2 * h] + b0 + rr.x,
                                                    acc[mt][nt][2 * h + 1] + b1 + rr.y);
            }
        }
    }
}

// ================= launch =================
extern "C" void kernel_launch(void* const* d_in, const int* in_sizes, int n_in,
                              void* d_out, int out_size) {
    const float* x     = (const float*)d_in[0];
    const float* gamma = (const float*)d_in[1];
    const float* beta  = (const float*)d_in[2];
    const float* wq    = (const float*)d_in[3];
    const float* bq    = (const float*)d_in[4];
    const float* wk    = (const float*)d_in[5];
    const float* bk    = (const float*)d_in[6];
    const float* wv    = (const float*)d_in[7];
    const float* bv    = (const float*)d_in[8];
    const float* wp    = (const float*)d_in[9];
    const float* bp    = (const float*)d_in[10];
    float* out = (float*)d_out;

    __nv_bfloat16 *p_qh, *p_kh, *p_vh, *p_wh;
    cudaGetSymbolAddress((void**)&p_qh, g_qh);
    cudaGetSymbolAddress((void**)&p_kh, g_kh);
    cudaGetSymbolAddress((void**)&p_vh, g_vh);
    cudaGetSymbolAddress((void**)&p_wh, g_wh);

    cudaFuncSetAttribute(flash_mma, cudaFuncAttributeMaxDynamicSharedMemorySize, FL_SMEM);
    cudaFuncSetAttribute(qkv_tc,    cudaFuncAttributeMaxDynamicSharedMemorySize, QKV_SMEM);

    gn_stats_convw<<<512, 256>>>(x, wq, wk, wv, wp);

    qkv_tc<<<128, 256, QKV_SMEM>>>(x, gamma, beta, p_wh, bq, bk, bv, p_qh, p_kh, p_vh);

    flash_mma<<<dim3(32, 4), 256, FL_SMEM>>>(p_qh, p_kh, p_vh, p_wh + 196608, bp, x, out);
}